// round 3
// baseline (speedup 1.0000x reference)
#include <cuda_runtime.h>
#include <stdint.h>

#define NN 100000
#define NE 3200000
#define F  16
#define SCAN_T 1024
#define CHUNK  98   // 1024 * 98 = 100352 >= NN

// Scratch (allocation-free rule: __device__ globals)
__device__ __align__(16) int   d_deg[NN];
__device__ __align__(16) int   d_rowptr[NN];
__device__ __align__(16) int   d_cursor[NN];
__device__ __align__(16) int   d_csr[NE];
__device__ __align__(16) float d_dis[NN];
__device__ __align__(16) float d_g[NN * F];
__device__ __align__(16) float d_acc[NN * F];

__global__ void k_zero_deg() {
    int i = blockIdx.x * blockDim.x + threadIdx.x;
    if (i < NN) d_deg[i] = 0;
}

// Pass 1 over edge_index (int32!): in-degree of dst (int reduction -> REDG)
__global__ void k_count(const int* __restrict__ ei) {
    int e = blockIdx.x * blockDim.x + threadIdx.x;
    if (e >= NE) return;
    int d = ei[NE + e];
    atomicAdd(&d_deg[d], 1);
}

// Single-block exclusive scan over deg -> rowptr & cursor; also dis = rsqrt(deg+1)
__global__ void k_scan() {
    __shared__ int ssum[SCAN_T];
    int t = threadIdx.x;
    int base = t * CHUNK;
    int local = 0;
    for (int j = 0; j < CHUNK; j++) {
        int i = base + j;
        if (i < NN) local += d_deg[i];
    }
    ssum[t] = local;
    __syncthreads();
    // Hillis-Steele inclusive scan
    for (int d = 1; d < SCAN_T; d <<= 1) {
        int v = 0;
        if (t >= d) v = ssum[t - d];
        __syncthreads();
        ssum[t] += v;
        __syncthreads();
    }
    int run = ssum[t] - local;  // exclusive prefix for this thread's chunk
    for (int j = 0; j < CHUNK; j++) {
        int i = base + j;
        if (i < NN) {
            int dg = d_deg[i];
            d_rowptr[i] = run;
            d_cursor[i] = run;
            d_dis[i] = rsqrtf((float)(dg + 1));
            run += dg;
        }
    }
}

// Pass 2 over edge_index: bucket src by dst
__global__ void k_fill(const int* __restrict__ ei) {
    int e = blockIdx.x * blockDim.x + threadIdx.x;
    if (e >= NE) return;
    int s = ei[e];
    int d = ei[NE + e];
    int slot = atomicAdd(&d_cursor[d], 1);
    d_csr[slot] = s;
}

// Layer-1 init: h = x@W1; g = dis*h
__global__ void k_l1_init(const float* __restrict__ x, const float* __restrict__ W1) {
    __shared__ float sW[F * F];
    int t = threadIdx.x;
    if (t < F * F) sW[t] = W1[t];
    __syncthreads();
    int i = blockIdx.x * blockDim.x + t;
    if (i >= NN) return;

    float dis = d_dis[i];
    float xi[F];
#pragma unroll
    for (int k = 0; k < F; k++) xi[k] = x[(size_t)i * F + k];

    float h[F];
#pragma unroll
    for (int j = 0; j < F; j++) {
        float a = 0.f;
#pragma unroll
        for (int k = 0; k < F; k++) a = fmaf(xi[k], sW[k * F + j], a);
        h[j] = a * dis;
    }
#pragma unroll
    for (int j = 0; j < F; j++) d_g[(size_t)i * F + j] = h[j];
}

// Gather: acc[i] = g[i] (self-loop) + sum_{e in row(i)} g[csr[e]]
// 4 threads per node, each owns one float4 feature chunk.
__global__ void k_gather() {
    int tid = blockIdx.x * blockDim.x + threadIdx.x;
    if (tid >= NN * 4) return;
    int i = tid >> 2;
    int q = tid & 3;

    const float4* __restrict__ G = (const float4*)d_g;
    float4 a = G[i * 4 + q];

    int e   = d_rowptr[i];
    int end = e + d_deg[i];

    int sn = (e < end) ? d_csr[e] : 0;
    while (e < end) {
        int s = sn;
        ++e;
        sn = (e < end) ? d_csr[e] : 0;   // prefetch next index
        float4 v = G[s * 4 + q];
        a.x += v.x; a.y += v.y; a.z += v.z; a.w += v.w;
    }
    ((float4*)d_acc)[i * 4 + q] = a;
}

// Finalize layer 1 + start layer 2: h1 = relu(dis*acc + b1); g = dis*(h1@W2)
__global__ void k_mid(const float* __restrict__ b1, const float* __restrict__ W2) {
    __shared__ float sW[F * F];
    __shared__ float sb[F];
    int t = threadIdx.x;
    if (t < F * F) sW[t] = W2[t];
    if (t < F) sb[t] = b1[t];
    __syncthreads();
    int i = blockIdx.x * blockDim.x + t;
    if (i >= NN) return;

    float dis = d_dis[i];
    float h1[F];
#pragma unroll
    for (int k = 0; k < F; k++)
        h1[k] = fmaxf(fmaf(dis, d_acc[(size_t)i * F + k], sb[k]), 0.f);

    float h2[F];
#pragma unroll
    for (int j = 0; j < F; j++) {
        float a = 0.f;
#pragma unroll
        for (int k = 0; k < F; k++) a = fmaf(h1[k], sW[k * F + j], a);
        h2[j] = a * dis;
    }
#pragma unroll
    for (int j = 0; j < F; j++) d_g[(size_t)i * F + j] = h2[j];
}

// Finalize layer 2 + FC head: out[i] = relu(dis*acc + b2) . Wfc + bfc
__global__ void k_final(const float* __restrict__ b2, const float* __restrict__ Wfc,
                        const float* __restrict__ bfc, float* __restrict__ out) {
    __shared__ float sb[F];
    __shared__ float sw[F];
    __shared__ float sbias;
    int t = threadIdx.x;
    if (t < F) { sb[t] = b2[t]; sw[t] = Wfc[t]; }
    if (t == 0) sbias = bfc[0];
    __syncthreads();
    int i = blockIdx.x * blockDim.x + t;
    if (i >= NN) return;

    float dis = d_dis[i];
    float a = 0.f;
#pragma unroll
    for (int k = 0; k < F; k++) {
        float h = fmaxf(fmaf(dis, d_acc[(size_t)i * F + k], sb[k]), 0.f);
        a = fmaf(h, sw[k], a);
    }
    out[i] = a + sbias;
}

extern "C" void kernel_launch(void* const* d_in, const int* in_sizes, int n_in,
                              void* d_out, int out_size) {
    const float* x   = (const float*)d_in[0];
    const int*   ei  = (const int*)d_in[1];     // int32! (JAX x64 disabled)
    const float* W1  = (const float*)d_in[2];
    const float* b1  = (const float*)d_in[3];
    const float* W2  = (const float*)d_in[4];
    const float* b2  = (const float*)d_in[5];
    const float* Wfc = (const float*)d_in[6];
    const float* bfc = (const float*)d_in[7];
    float* out = (float*)d_out;

    const int TB = 256;
    const int nodeBlocks   = (NN + TB - 1) / TB;
    const int edgeBlocks   = (NE + TB - 1) / TB;
    const int gatherBlocks = (NN * 4 + TB - 1) / TB;

    k_zero_deg<<<nodeBlocks, TB>>>();
    k_count<<<edgeBlocks, TB>>>(ei);
    k_scan<<<1, SCAN_T>>>();
    k_fill<<<edgeBlocks, TB>>>(ei);
    k_l1_init<<<nodeBlocks, TB>>>(x, W1);
    k_gather<<<gatherBlocks, TB>>>();
    k_mid<<<nodeBlocks, TB>>>(b1, W2);
    k_gather<<<gatherBlocks, TB>>>();
    k_final<<<nodeBlocks, TB>>>(b2, Wfc, bfc, out);
}

// round 4
// speedup vs baseline: 2.6209x; 2.6209x over previous
#include <cuda_runtime.h>
#include <stdint.h>

#define NN 100000
#define NE 3200000
#define F  16
#define NBLK ((NN + 255) / 256)   // 391 node blocks

// Scratch (allocation-free rule: __device__ globals)
__device__ __align__(16) int   d_deg[NN];
__device__ __align__(16) int   d_rowptr[NN];
__device__ __align__(16) int   d_off[NE];
__device__ __align__(16) int   d_csr[NE];
__device__ __align__(16) int   d_bsum[NBLK];
__device__ __align__(16) int   d_boff[NBLK];
__device__ __align__(16) float d_dis[NN];
__device__ __align__(16) float d_g[NN * F];
__device__ __align__(16) float d_acc[NN * F];

__global__ void k_zero_deg() {
    int i = blockIdx.x * blockDim.x + threadIdx.x;
    if (i < NN) d_deg[i] = 0;
}

// Pass 1: occurrence index within dst bucket + final in-degree
__global__ void k_count(const int* __restrict__ ei) {
    int e = blockIdx.x * blockDim.x + threadIdx.x;
    if (e >= NE) return;
    int d = ei[NE + e];
    d_off[e] = atomicAdd(&d_deg[d], 1);
}

// Scan stage 1: per-256-block exclusive scan of deg; block totals; dis = rsqrt(deg+1)
__global__ void k_scan1() {
    __shared__ int s[256];
    int t = threadIdx.x;
    int i = blockIdx.x * 256 + t;
    int dg = (i < NN) ? d_deg[i] : 0;
    s[t] = dg;
    __syncthreads();
    for (int off = 1; off < 256; off <<= 1) {
        int v = (t >= off) ? s[t - off] : 0;
        __syncthreads();
        s[t] += v;
        __syncthreads();
    }
    if (i < NN) {
        d_rowptr[i] = s[t] - dg;               // exclusive within block
        d_dis[i] = rsqrtf((float)(dg + 1));
    }
    if (t == 255) d_bsum[blockIdx.x] = s[255];
}

// Scan stage 2: single block scans the 391 block sums
__global__ void k_scan2() {
    __shared__ int s[512];
    int t = threadIdx.x;
    int v = (t < NBLK) ? d_bsum[t] : 0;
    s[t] = v;
    __syncthreads();
    for (int off = 1; off < 512; off <<= 1) {
        int u = (t >= off) ? s[t - off] : 0;
        __syncthreads();
        s[t] += u;
        __syncthreads();
    }
    if (t < NBLK) d_boff[t] = s[t] - v;        // exclusive
}

// Scan stage 3: add block offsets
__global__ void k_scan3() {
    int i = blockIdx.x * 256 + threadIdx.x;
    if (i < NN) d_rowptr[i] += d_boff[blockIdx.x];
}

// Pass 2: atomic-free CSR fill
__global__ void k_fill(const int* __restrict__ ei) {
    int e = blockIdx.x * blockDim.x + threadIdx.x;
    if (e >= NE) return;
    int s = ei[e];
    int d = ei[NE + e];
    d_csr[d_rowptr[d] + d_off[e]] = s;
}

// Layer-1 init: h = x@W1; g = dis*h
__global__ void k_l1_init(const float* __restrict__ x, const float* __restrict__ W1) {
    __shared__ float sW[F * F];
    int t = threadIdx.x;
    if (t < F * F) sW[t] = W1[t];
    __syncthreads();
    int i = blockIdx.x * blockDim.x + t;
    if (i >= NN) return;

    float dis = d_dis[i];
    float xi[F];
#pragma unroll
    for (int k = 0; k < F; k++) xi[k] = x[(size_t)i * F + k];

    float h[F];
#pragma unroll
    for (int j = 0; j < F; j++) {
        float a = 0.f;
#pragma unroll
        for (int k = 0; k < F; k++) a = fmaf(xi[k], sW[k * F + j], a);
        h[j] = a * dis;
    }
#pragma unroll
    for (int j = 0; j < F; j++) d_g[(size_t)i * F + j] = h[j];
}

// Warp-per-node gather: acc[i] = g[i] + sum_{e in row(i)} g[csr[e]]
// lane = j*4 + q : lane group j (0..7) strides edges, q (0..3) owns a float4 chunk.
__global__ void k_gather() {
    int gtid = blockIdx.x * blockDim.x + threadIdx.x;
    int w = gtid >> 5;
    if (w >= NN) return;
    int lane = threadIdx.x & 31;
    int q = lane & 3;
    int j = lane >> 2;

    const float4* __restrict__ G = (const float4*)d_g;
    float4 a = make_float4(0.f, 0.f, 0.f, 0.f);

    int beg = d_rowptr[w];
    int end = beg + d_deg[w];
    for (int e = beg + j; e < end; e += 8) {
        int s = d_csr[e];
        float4 v = G[s * 4 + q];
        a.x += v.x; a.y += v.y; a.z += v.z; a.w += v.w;
    }
#pragma unroll
    for (int off = 16; off >= 4; off >>= 1) {
        a.x += __shfl_down_sync(0xffffffffu, a.x, off);
        a.y += __shfl_down_sync(0xffffffffu, a.y, off);
        a.z += __shfl_down_sync(0xffffffffu, a.z, off);
        a.w += __shfl_down_sync(0xffffffffu, a.w, off);
    }
    if (lane < 4) {                    // lane == q here
        float4 g0 = G[w * 4 + lane];   // self-loop
        a.x += g0.x; a.y += g0.y; a.z += g0.z; a.w += g0.w;
        ((float4*)d_acc)[w * 4 + lane] = a;
    }
}

// Finalize layer 1 + start layer 2: h1 = relu(dis*acc + b1); g = dis*(h1@W2)
__global__ void k_mid(const float* __restrict__ b1, const float* __restrict__ W2) {
    __shared__ float sW[F * F];
    __shared__ float sb[F];
    int t = threadIdx.x;
    if (t < F * F) sW[t] = W2[t];
    if (t < F) sb[t] = b1[t];
    __syncthreads();
    int i = blockIdx.x * blockDim.x + t;
    if (i >= NN) return;

    float dis = d_dis[i];
    float h1[F];
#pragma unroll
    for (int k = 0; k < F; k++)
        h1[k] = fmaxf(fmaf(dis, d_acc[(size_t)i * F + k], sb[k]), 0.f);

    float h2[F];
#pragma unroll
    for (int j = 0; j < F; j++) {
        float a = 0.f;
#pragma unroll
        for (int k = 0; k < F; k++) a = fmaf(h1[k], sW[k * F + j], a);
        h2[j] = a * dis;
    }
#pragma unroll
    for (int j = 0; j < F; j++) d_g[(size_t)i * F + j] = h2[j];
}

// Finalize layer 2 + FC head: out[i] = relu(dis*acc + b2) . Wfc + bfc
__global__ void k_final(const float* __restrict__ b2, const float* __restrict__ Wfc,
                        const float* __restrict__ bfc, float* __restrict__ out) {
    __shared__ float sb[F];
    __shared__ float sw[F];
    __shared__ float sbias;
    int t = threadIdx.x;
    if (t < F) { sb[t] = b2[t]; sw[t] = Wfc[t]; }
    if (t == 0) sbias = bfc[0];
    __syncthreads();
    int i = blockIdx.x * blockDim.x + t;
    if (i >= NN) return;

    float dis = d_dis[i];
    float a = 0.f;
#pragma unroll
    for (int k = 0; k < F; k++) {
        float h = fmaxf(fmaf(dis, d_acc[(size_t)i * F + k], sb[k]), 0.f);
        a = fmaf(h, sw[k], a);
    }
    out[i] = a + sbias;
}

extern "C" void kernel_launch(void* const* d_in, const int* in_sizes, int n_in,
                              void* d_out, int out_size) {
    const float* x   = (const float*)d_in[0];
    const int*   ei  = (const int*)d_in[1];     // int32 (JAX x64 disabled)
    const float* W1  = (const float*)d_in[2];
    const float* b1  = (const float*)d_in[3];
    const float* W2  = (const float*)d_in[4];
    const float* b2  = (const float*)d_in[5];
    const float* Wfc = (const float*)d_in[6];
    const float* bfc = (const float*)d_in[7];
    float* out = (float*)d_out;

    const int TB = 256;
    const int nodeBlocks   = NBLK;
    const int edgeBlocks   = (NE + TB - 1) / TB;
    const int gatherBlocks = (NN * 32 + TB - 1) / TB;

    k_zero_deg<<<nodeBlocks, TB>>>();
    k_count<<<edgeBlocks, TB>>>(ei);
    k_scan1<<<nodeBlocks, TB>>>();
    k_scan2<<<1, 512>>>();
    k_scan3<<<nodeBlocks, TB>>>();
    k_fill<<<edgeBlocks, TB>>>(ei);
    k_l1_init<<<nodeBlocks, TB>>>(x, W1);
    k_gather<<<gatherBlocks, TB>>>();
    k_mid<<<nodeBlocks, TB>>>(b1, W2);
    k_gather<<<gatherBlocks, TB>>>();
    k_final<<<nodeBlocks, TB>>>(b2, Wfc, bfc, out);
}